// round 8
// baseline (speedup 1.0000x reference)
#include <cuda_runtime.h>
#include <cstdint>

namespace {
constexpr int Bn = 256, Tn = 64, Mn = 256, Hn = 256, K2H = 512, G4H = 1024;
constexpr int NSX = 8;   // split-K slices for x1 (K=512, slice 64)
constexpr int NSG = 4;   // split-K slices for G1 (K=256, slice 64)
}

// ---------------- device scratch (no allocations allowed) ----------------
__device__ float g_enc[Bn * Tn * Mn];       // enc (b,t,m)
__device__ float g_y1 [Bn * Tn * Mn];       // enc @ U_d^T
__device__ float g_S  [Bn * K2H];           // [d | sp] per batch row
__device__ float g_x1p[NSX * Bn * Mn];      // x1 split-K partials
__device__ float g_G1p[NSG * Bn * G4H];     // G1 split-K partials
__device__ float g_c  [Bn * Mn];            // last context (for k_out)
__device__ float g_gbias[G4H];              // b_ih + b_hh
__device__ float g_wv [513];                // folded W_y/v_y projection + const

// tf32 fragment-ordered weights (prepped once per launch)
__device__ float g_Wdf[(Mn / 8) * (K2H / 8) * 64];   // W_d   [256 x 512]
__device__ float g_Whf[(G4H / 8) * (Hn / 8) * 64];   // W_hh  [1024 x 256]
__device__ float g_Udf[(Mn / 8) * (Mn / 8) * 64];    // U_d   [256 x 256]

__device__ __forceinline__ float tanh_mufu(float x) {      // attention only
    float y; asm("tanh.approx.f32 %0, %1;" : "=f"(y) : "f"(x)); return y;
}
__device__ __forceinline__ float tanh_acc(float x) {       // LSTM gates
    float e = __expf(2.f * x);
    return 1.f - __fdividef(2.f, e + 1.f);
}
__device__ __forceinline__ float sigm(float x) {
    return __fdividef(1.f, 1.f + __expf(-x));
}
__device__ __forceinline__ uint32_t to_tf32(float f) {
    uint32_t u; asm("cvt.rna.tf32.f32 %0, %1;" : "=r"(u) : "f"(f)); return u;
}
__device__ __forceinline__ void mma_tf32(float acc[4], uint4 a,
                                         uint32_t b0, uint32_t b1) {
    asm volatile(
        "mma.sync.aligned.m16n8k8.row.col.f32.tf32.tf32.f32 "
        "{%0,%1,%2,%3}, {%4,%5,%6,%7}, {%8,%9}, {%0,%1,%2,%3};"
        : "+f"(acc[0]), "+f"(acc[1]), "+f"(acc[2]), "+f"(acc[3])
        : "r"(a.x), "r"(a.y), "r"(a.z), "r"(a.w), "r"(b0), "r"(b1));
}

// ---------------- prep: transpose enc, zero state, fold gate bias --------
__global__ void k_pre(const float* __restrict__ enc_in,
                      const float* __restrict__ b_ih,
                      const float* __restrict__ b_hh) {
    int idx = blockIdx.x * blockDim.x + threadIdx.x;
    int stride = gridDim.x * blockDim.x;
    for (int i = idx; i < Bn * Tn * Mn; i += stride) {
        int m = i & (Mn - 1);
        int t = (i >> 8) & (Tn - 1);
        int b = i >> 14;
        g_enc[i] = enc_in[(size_t)t * Bn * Mn + (size_t)b * Mn + m];
    }
    for (int i = idx; i < Bn * K2H; i += stride) g_S[i] = 0.f;
    for (int i = idx; i < G4H; i += stride) g_gbias[i] = b_ih[i] + b_hh[i];
}

// ---------------- fold final projection ----------------------------------
__global__ void k_wv(const float* __restrict__ W_y, const float* __restrict__ v_y,
                     const float* __restrict__ b_Wy, const float* __restrict__ b_vy) {
    int k = threadIdx.x;  // 512 threads
    float s = 0.f;
    for (int j = 0; j < Hn; j++) s += v_y[j] * W_y[(size_t)j * K2H + k];
    g_wv[k] = s;
    if (k == 0) {
        float s0 = 0.f;
        for (int j = 0; j < Hn; j++) s0 += v_y[j] * b_Wy[j];
        g_wv[512] = s0 + b_vy[0];
    }
}

// ---------------- weight -> tf32 fragment order ---------------------------
// dst resolved ON DEVICE (never pass __device__ symbols from host!).
// dst[((j8*(K/8)+kk)*32+lane)*2 + r]:
//   b0 = W[j8*8 + lane/4][kk*8 + lane%4], b1 = same row, k+4  (tf32)
__global__ void k_mkfrag(const float* __restrict__ src, int which,
                         int N, int K) {
    float* dst = (which == 0) ? g_Wdf : (which == 1) ? g_Whf : g_Udf;
    int id = blockIdx.x * blockDim.x + threadIdx.x;
    int total = (N >> 3) * (K >> 3) * 32;
    if (id >= total) return;
    int lane = id & 31;
    int kk = (id >> 5) % (K >> 3);
    int j8 = (id >> 5) / (K >> 3);
    int n  = j8 * 8 + (lane >> 2);
    int k0 = kk * 8 + (lane & 3);
    dst[id * 2 + 0] = __uint_as_float(to_tf32(src[(size_t)n * K + k0]));
    dst[id * 2 + 1] = __uint_as_float(to_tf32(src[(size_t)n * K + k0 + 4]));
}

// ---- tf32 MMA job: C[m0..+64, n0..+64] = A[.,kb..] * W^T slice (fp32 acc)
// 128 threads / 4 warps; warp w owns rows m0+16w..+16. A staged to SMEM in
// fragment order (one LDS.128 per k-iter); B frags streamed from prepped
// global arrays (coalesced LDG.64, double-buffered across k-iters).
__device__ __forceinline__ void mma_job(
    const float* __restrict__ A, int lda, int kb, int ksl,
    const float* __restrict__ Wf, int Kfr,     // Kfr = K/8 of weight
    float* __restrict__ C, int ldc, int m0, int n0) {

    __shared__ __align__(16) uint32_t Af[4096];   // [w][kk][lane][reg], 16KB

    const int tid = threadIdx.x;
    const int w = tid >> 5, lane = tid & 31;

    float acc[8][4];
#pragma unroll
    for (int j = 0; j < 8; j++)
#pragma unroll
        for (int q = 0; q < 4; q++) acc[j][q] = 0.f;

    const int r = tid >> 1;                    // staging row 0..63
    const int khalf = (tid & 1) * 32;          // staging k offset
    const int wv = r >> 4;
    const int lanebase = (r & 7) * 4;
    const int regbase0 = (r & 15) >> 3;

    const int nchunks = ksl >> 6;
    for (int c = 0; c < nchunks; c++) {
        if (c) __syncthreads();
        const float* Ap = A + (size_t)(m0 + r) * lda + kb + c * 64 + khalf;
#pragma unroll
        for (int i = 0; i < 8; i++) {
            float4 v = *(const float4*)(Ap + i * 4);
            int kloc = khalf + i * 4;
            int kk = kloc >> 3;
            int reg = regbase0 + ((kloc & 7) >> 2) * 2;
            uint32_t* dp = Af + ((wv * 8 + kk) * 32 + lanebase) * 4 + reg;
            dp[0]  = to_tf32(v.x);
            dp[4]  = to_tf32(v.y);
            dp[8]  = to_tf32(v.z);
            dp[12] = to_tf32(v.w);
        }
        __syncthreads();

        const int kkb = (kb + c * 64) >> 3;
        const float* bp = Wf + ((size_t)(n0 >> 3) * Kfr + kkb) * 64 + lane * 2;

        uint32_t bc[8][2];
#pragma unroll
        for (int j = 0; j < 8; j++) {
            const float* p = bp + (size_t)j * Kfr * 64;
            bc[j][0] = __float_as_uint(p[0]);
            bc[j][1] = __float_as_uint(p[1]);
        }
#pragma unroll
        for (int kkl = 0; kkl < 8; kkl++) {
            uint4 av = *(const uint4*)(Af + ((w * 8 + kkl) * 32 + lane) * 4);
            uint32_t bn[8][2];
            if (kkl < 7) {
#pragma unroll
                for (int j = 0; j < 8; j++) {
                    const float* p = bp + (size_t)j * Kfr * 64 + (kkl + 1) * 64;
                    bn[j][0] = __float_as_uint(p[0]);
                    bn[j][1] = __float_as_uint(p[1]);
                }
            }
#pragma unroll
            for (int j = 0; j < 8; j++) mma_tf32(acc[j], av, bc[j][0], bc[j][1]);
            if (kkl < 7) {
#pragma unroll
                for (int j = 0; j < 8; j++) { bc[j][0] = bn[j][0]; bc[j][1] = bn[j][1]; }
            }
        }
    }

    const int mrow = m0 + w * 16 + (lane >> 2);
    const int nc0  = n0 + (lane & 3) * 2;
#pragma unroll
    for (int j = 0; j < 8; j++) {
        float2 v0; v0.x = acc[j][0]; v0.y = acc[j][1];
        float2 v1; v1.x = acc[j][2]; v1.y = acc[j][3];
        *(float2*)(C + (size_t)mrow * ldc + nc0 + j * 8) = v0;
        *(float2*)(C + (size_t)(mrow + 8) * ldc + nc0 + j * 8) = v1;
    }
}

// ---------------- per-step fused GEMM, 64x64x64 tf32 jobs -----------------
// blocks 0..127  : x1 partials  (4m x 4n x 8 K-slices)
// blocks 128..383: G1 partials  (4m x 16n x 4 K-slices)
__global__ void __launch_bounds__(128) k_stepgemm() {
    const int id = blockIdx.x;
    if (id < 128) {
        int s  = id & 7;
        int n0 = ((id >> 3) & 3) * 64;
        int m0 = (id >> 5) * 64;
        mma_job(g_S, K2H, s * 64, 64, g_Wdf, K2H / 8,
                g_x1p + s * (Bn * Mn), Mn, m0, n0);
    } else {
        int j  = id - 128;
        int s  = j & 3;
        int n0 = ((j >> 2) & 15) * 64;
        int m0 = (j >> 6) * 64;
        mma_job(g_S, K2H, s * 64, 64, g_Whf, Hn / 8,
                g_G1p + s * (Bn * G4H), G4H, m0, n0);
    }
}

// ---------------- one-time y1 GEMM (tf32) ----------------------------------
__global__ void __launch_bounds__(128) k_y1() {
    int id = blockIdx.x;                 // 1024 blocks
    int m0 = (id >> 2) * 64;
    int n0 = (id & 3) * 64;
    mma_job(g_enc, Mn, 0, Mn, g_Udf, Mn / 8, g_y1, Mn, m0, n0);
}

// ---------------- per-batch attention + LSTM cell update ------------------
__global__ void __launch_bounds__(256) k_attn(
        const float* __restrict__ y_in, const float* __restrict__ v_d,
        const float* __restrict__ w_til, const float* __restrict__ b_wt,
        const float* __restrict__ W_ih, const float* __restrict__ b_Wd,
        int t_step) {
    int b = blockIdx.x, tid = threadIdx.x;
    int warp = tid >> 5, lane = tid & 31;
    __shared__ float sx[Mn], sv[Mn], sl[Tn], sred[8];
    __shared__ float s_ytil;

    {   // x1 = sum of NSX split-K partials + bias
        int o = b * Mn + tid;
        float v = b_Wd[tid];
#pragma unroll
        for (int s = 0; s < NSX; s++) v += g_x1p[s * (Bn * Mn) + o];
        sx[tid] = v;
    }
    sv[tid] = v_d[tid];
    __syncthreads();

    const float* y1b = g_y1 + (size_t)b * Tn * Mn;
#pragma unroll
    for (int i = 0; i < 8; i++) {
        int t = warp * 8 + i;
        const float* row = y1b + t * Mn;
        float acc = 0.f;
#pragma unroll
        for (int j = 0; j < 8; j++) {
            int m = lane + 32 * j;
            acc += tanh_mufu(sx[m] + row[m]) * sv[m];
        }
#pragma unroll
        for (int o = 16; o > 0; o >>= 1) acc += __shfl_xor_sync(0xffffffffu, acc, o);
        if (lane == 0) sl[t] = acc;
    }
    __syncthreads();

    if (warp == 0) {   // softmax over 64
        float v0 = sl[lane], v1 = sl[lane + 32];
        float mx = fmaxf(v0, v1);
#pragma unroll
        for (int o = 16; o > 0; o >>= 1) mx = fmaxf(mx, __shfl_xor_sync(0xffffffffu, mx, o));
        float e0 = __expf(v0 - mx), e1 = __expf(v1 - mx);
        float s = e0 + e1;
#pragma unroll
        for (int o = 16; o > 0; o >>= 1) s += __shfl_xor_sync(0xffffffffu, s, o);
        float inv = __fdividef(1.f, s);
        sl[lane] = e0 * inv; sl[lane + 32] = e1 * inv;
    }
    __syncthreads();

    const float* encb = g_enc + (size_t)b * Tn * Mn;
    float c = 0.f;
#pragma unroll 8
    for (int t = 0; t < Tn; t++) c += sl[t] * encb[t * Mn + tid];
    g_c[b * Mn + tid] = c;

    float part = c * w_til[tid];
#pragma unroll
    for (int o = 16; o > 0; o >>= 1) part += __shfl_xor_sync(0xffffffffu, part, o);
    if (lane == 0) sred[warp] = part;
    __syncthreads();
    if (tid == 0) {
        float s = 0.f;
#pragma unroll
        for (int w = 0; w < 8; w++) s += sred[w];
        s_ytil = s + w_til[Mn] * y_in[b * Tn + t_step] + b_wt[0];
    }
    __syncthreads();
    float yt = s_ytil;

    float gate[4];
#pragma unroll
    for (int q = 0; q < 4; q++) {
        int idx = q * Hn + tid;
        float v = g_gbias[idx] + yt * W_ih[idx];
#pragma unroll
        for (int s = 0; s < NSG; s++)
            v += g_G1p[s * (Bn * G4H) + b * G4H + idx];
        gate[q] = v;
    }
    float sp = g_S[b * K2H + Hn + tid];
    float spn = sigm(gate[1]) * sp + sigm(gate[0]) * tanh_acc(gate[2]);
    float dn  = sigm(gate[3]) * tanh_acc(spn);
    g_S[b * K2H + tid]      = dn;
    g_S[b * K2H + Hn + tid] = spn;
}

// ---------------- folded output: out[b] = [d|c] . wv + const --------------
__global__ void k_out(float* __restrict__ out) {
    int b = blockIdx.x, tid = threadIdx.x;
    int warp = tid >> 5, lane = tid & 31;
    __shared__ float sred[8];
    float p = g_S[b * K2H + tid] * g_wv[tid] + g_c[b * Mn + tid] * g_wv[Hn + tid];
#pragma unroll
    for (int o = 16; o > 0; o >>= 1) p += __shfl_xor_sync(0xffffffffu, p, o);
    if (lane == 0) sred[warp] = p;
    __syncthreads();
    if (tid == 0) {
        float s = 0.f;
#pragma unroll
        for (int w = 0; w < 8; w++) s += sred[w];
        out[b] = s + g_wv[512];
    }
}

extern "C" void kernel_launch(void* const* d_in, const int* in_sizes, int n_in,
                              void* d_out, int out_size) {
    const float* enc  = (const float*)d_in[0];
    const float* y    = (const float*)d_in[1];
    const float* W_d  = (const float*)d_in[2];
    const float* b_Wd = (const float*)d_in[3];
    const float* U_d  = (const float*)d_in[4];
    const float* v_d  = (const float*)d_in[5];
    const float* w_t  = (const float*)d_in[6];
    const float* b_wt = (const float*)d_in[7];
    const float* W_ih = (const float*)d_in[8];
    const float* W_hh = (const float*)d_in[9];
    const float* b_ih = (const float*)d_in[10];
    const float* b_hh = (const float*)d_in[11];
    const float* W_y  = (const float*)d_in[12];
    const float* b_Wy = (const float*)d_in[13];
    const float* v_y  = (const float*)d_in[14];
    const float* b_vy = (const float*)d_in[15];

    k_pre<<<2048, 256>>>(enc, b_ih, b_hh);
    k_wv<<<1, 512>>>(W_y, v_y, b_Wy, b_vy);
    k_mkfrag<<<((Mn / 8) * (K2H / 8) * 32) / 256, 256>>>(W_d, 0, Mn, K2H);
    k_mkfrag<<<((G4H / 8) * (Hn / 8) * 32) / 256, 256>>>(W_hh, 1, G4H, Hn);
    k_mkfrag<<<((Mn / 8) * (Mn / 8) * 32) / 256, 256>>>(U_d, 2, Mn, Mn);
    k_y1<<<1024, 128>>>();
    for (int t = 0; t < Tn; t++) {
        k_stepgemm<<<384, 128>>>();
        k_attn<<<256, 256>>>(y, v_d, w_t, b_wt, W_ih, b_Wd, t);
    }
    k_out<<<256, 256>>>((float*)d_out);
}

// round 9
// speedup vs baseline: 1.1390x; 1.1390x over previous
#include <cuda_runtime.h>
#include <cstdint>

namespace {
constexpr int Bn = 256, Tn = 64, Mn = 256, Hn = 256, K2H = 512, G4H = 1024;
constexpr int NSX = 8;   // split-K slices for x1 (K=512, slice 64)
constexpr int NSG = 4;   // split-K slices for G1 (K=256, slice 64)
}

// ---------------- device scratch (no allocations allowed) ----------------
__device__ float g_enc[Bn * Tn * Mn];       // enc (b,t,m)
__device__ float g_y1 [Bn * Tn * Mn];       // enc @ U_d^T
__device__ float g_S  [Bn * K2H];           // [d | sp] per batch row
__device__ float g_x1p[NSX * Bn * Mn];      // x1 split-K partials
__device__ float g_G1p[NSG * Bn * G4H];     // G1 split-K partials
__device__ float g_c  [Bn * Mn];            // last context (for k_out)
__device__ float g_gbias[G4H];              // b_ih + b_hh
__device__ float g_wv [513];                // folded W_y/v_y projection + const

// tf32 fragment-ordered weights (prepped once per launch)
__device__ float g_Wdf[(Mn / 8) * (K2H / 8) * 64];   // W_d   [256 x 512]
__device__ float g_Whf[(G4H / 8) * (Hn / 8) * 64];   // W_hh  [1024 x 256]
__device__ float g_Udf[(Mn / 8) * (Mn / 8) * 64];    // U_d   [256 x 256]

__device__ __forceinline__ float tanh_mufu(float x) {      // attention only
    float y; asm("tanh.approx.f32 %0, %1;" : "=f"(y) : "f"(x)); return y;
}
__device__ __forceinline__ float tanh_acc(float x) {       // LSTM gates
    float e = __expf(2.f * x);
    return 1.f - __fdividef(2.f, e + 1.f);
}
__device__ __forceinline__ float sigm(float x) {
    return __fdividef(1.f, 1.f + __expf(-x));
}
__device__ __forceinline__ uint32_t to_tf32(float f) {
    uint32_t u; asm("cvt.rna.tf32.f32 %0, %1;" : "=r"(u) : "f"(f)); return u;
}
__device__ __forceinline__ void mma_tf32(float acc[4], uint4 a,
                                         uint32_t b0, uint32_t b1) {
    asm volatile(
        "mma.sync.aligned.m16n8k8.row.col.f32.tf32.tf32.f32 "
        "{%0,%1,%2,%3}, {%4,%5,%6,%7}, {%8,%9}, {%0,%1,%2,%3};"
        : "+f"(acc[0]), "+f"(acc[1]), "+f"(acc[2]), "+f"(acc[3])
        : "r"(a.x), "r"(a.y), "r"(a.z), "r"(a.w), "r"(b0), "r"(b1));
}

// ---------------- prep: transpose enc, zero state, fold gate bias --------
__global__ void k_pre(const float* __restrict__ enc_in,
                      const float* __restrict__ b_ih,
                      const float* __restrict__ b_hh) {
    int idx = blockIdx.x * blockDim.x + threadIdx.x;
    int stride = gridDim.x * blockDim.x;
    for (int i = idx; i < Bn * Tn * Mn; i += stride) {
        int m = i & (Mn - 1);
        int t = (i >> 8) & (Tn - 1);
        int b = i >> 14;
        g_enc[i] = enc_in[(size_t)t * Bn * Mn + (size_t)b * Mn + m];
    }
    for (int i = idx; i < Bn * K2H; i += stride) g_S[i] = 0.f;
    for (int i = idx; i < G4H; i += stride) g_gbias[i] = b_ih[i] + b_hh[i];
}

// ---------------- fold final projection ----------------------------------
__global__ void k_wv(const float* __restrict__ W_y, const float* __restrict__ v_y,
                     const float* __restrict__ b_Wy, const float* __restrict__ b_vy) {
    int k = threadIdx.x;  // 512 threads
    float s = 0.f;
    for (int j = 0; j < Hn; j++) s += v_y[j] * W_y[(size_t)j * K2H + k];
    g_wv[k] = s;
    if (k == 0) {
        float s0 = 0.f;
        for (int j = 0; j < Hn; j++) s0 += v_y[j] * b_Wy[j];
        g_wv[512] = s0 + b_vy[0];
    }
}

// ---------------- weight -> tf32 fragment order ---------------------------
// dst resolved ON DEVICE (never pass __device__ symbols from host!).
// dst[((j8*(K/8)+kk)*32+lane)*2 + r]:
//   b0 = W[j8*8 + lane/4][kk*8 + lane%4], b1 = same row, k+4  (tf32)
__global__ void k_mkfrag(const float* __restrict__ src, int which,
                         int N, int K) {
    float* dst = (which == 0) ? g_Wdf : (which == 1) ? g_Whf : g_Udf;
    int id = blockIdx.x * blockDim.x + threadIdx.x;
    int total = (N >> 3) * (K >> 3) * 32;
    if (id >= total) return;
    int lane = id & 31;
    int kk = (id >> 5) % (K >> 3);
    int j8 = (id >> 5) / (K >> 3);
    int n  = j8 * 8 + (lane >> 2);
    int k0 = kk * 8 + (lane & 3);
    dst[id * 2 + 0] = __uint_as_float(to_tf32(src[(size_t)n * K + k0]));
    dst[id * 2 + 1] = __uint_as_float(to_tf32(src[(size_t)n * K + k0 + 4]));
}

// ---- tf32 MMA job: C[m0..+64, n0..+64] = A[.,kb..] * W^T slice (fp32 acc)
// 128 threads / 4 warps; warp w owns rows m0+16w..+16. Both A and B frags
// staged to SMEM per 64-K chunk (B copy is fully contiguous+coalesced from
// the prepped global layout; one ~300cyc LDG exposure per job instead of
// per-k-iter L2 stalls). Inner loop is pure LDS + MMA.
__device__ __forceinline__ void mma_job(
    const float* __restrict__ A, int lda, int kb, int ksl,
    const float* __restrict__ Wf, int Kfr,     // Kfr = K/8 of weight
    float* __restrict__ C, int ldc, int m0, int n0) {

    __shared__ __align__(16) uint32_t Af[4096];   // A frags, 16KB
    __shared__ __align__(16) float    Bf[4096];   // B frags, 16KB

    const int tid = threadIdx.x;
    const int w = tid >> 5, lane = tid & 31;

    float acc[8][4];
#pragma unroll
    for (int j = 0; j < 8; j++)
#pragma unroll
        for (int q = 0; q < 4; q++) acc[j][q] = 0.f;

    const int r = tid >> 1;                    // A staging row 0..63
    const int khalf = (tid & 1) * 32;          // A staging k offset
    const int wv = r >> 4;
    const int lanebase = (r & 7) * 4;
    const int regbase0 = (r & 15) >> 3;

    const int nchunks = ksl >> 6;
    for (int c = 0; c < nchunks; c++) {
        if (c) __syncthreads();

        // issue all A loads (8 indep float4) and B loads (8 indep float4)
        const float* Ap = A + (size_t)(m0 + r) * lda + kb + c * 64 + khalf;
        float4 av8[8];
#pragma unroll
        for (int i = 0; i < 8; i++) av8[i] = *(const float4*)(Ap + i * 4);

        const int kkb = (kb + c * 64) >> 3;
        float4 bv8[8];
#pragma unroll
        for (int it = 0; it < 8; it++) {
            int idx = tid + it * 128;          // float4 unit 0..1023
            int chunk = idx >> 4;              // = j*8 + kkl
            int j = chunk >> 3, kkl = chunk & 7;
            const float* sp = Wf
                + ((size_t)((n0 >> 3) + j) * Kfr + kkb + kkl) * 64
                + (idx & 15) * 4;
            bv8[it] = *(const float4*)sp;
        }

        // deposit A (fragment order) and B (contiguous)
#pragma unroll
        for (int i = 0; i < 8; i++) {
            int kloc = khalf + i * 4;
            int kk = kloc >> 3;
            int reg = regbase0 + ((kloc & 7) >> 2) * 2;
            uint32_t* dp = Af + ((wv * 8 + kk) * 32 + lanebase) * 4 + reg;
            dp[0]  = to_tf32(av8[i].x);
            dp[4]  = to_tf32(av8[i].y);
            dp[8]  = to_tf32(av8[i].z);
            dp[12] = to_tf32(av8[i].w);
        }
#pragma unroll
        for (int it = 0; it < 8; it++) {
            int idx = tid + it * 128;
            *(float4*)(Bf + (idx << 2)) = bv8[it];
        }
        __syncthreads();

        // pure LDS + MMA inner loop
#pragma unroll
        for (int kkl = 0; kkl < 8; kkl++) {
            uint4 av = *(const uint4*)(Af + ((w * 8 + kkl) * 32 + lane) * 4);
#pragma unroll
            for (int j = 0; j < 8; j++) {
                float2 b = *(const float2*)(Bf + (j * 8 + kkl) * 64 + lane * 2);
                mma_tf32(acc[j], av, __float_as_uint(b.x), __float_as_uint(b.y));
            }
        }
    }

    const int mrow = m0 + w * 16 + (lane >> 2);
    const int nc0  = n0 + (lane & 3) * 2;
#pragma unroll
    for (int j = 0; j < 8; j++) {
        float2 v0; v0.x = acc[j][0]; v0.y = acc[j][1];
        float2 v1; v1.x = acc[j][2]; v1.y = acc[j][3];
        *(float2*)(C + (size_t)mrow * ldc + nc0 + j * 8) = v0;
        *(float2*)(C + (size_t)(mrow + 8) * ldc + nc0 + j * 8) = v1;
    }
}

// ---------------- per-step fused GEMM, 64x64x64 tf32 jobs -----------------
// blocks 0..127  : x1 partials  (4m x 4n x 8 K-slices)
// blocks 128..383: G1 partials  (4m x 16n x 4 K-slices)
__global__ void __launch_bounds__(128) k_stepgemm() {
    const int id = blockIdx.x;
    if (id < 128) {
        int s  = id & 7;
        int n0 = ((id >> 3) & 3) * 64;
        int m0 = (id >> 5) * 64;
        mma_job(g_S, K2H, s * 64, 64, g_Wdf, K2H / 8,
                g_x1p + s * (Bn * Mn), Mn, m0, n0);
    } else {
        int j  = id - 128;
        int s  = j & 3;
        int n0 = ((j >> 2) & 15) * 64;
        int m0 = (j >> 6) * 64;
        mma_job(g_S, K2H, s * 64, 64, g_Whf, Hn / 8,
                g_G1p + s * (Bn * G4H), G4H, m0, n0);
    }
}

// ---------------- one-time y1 GEMM (tf32) ----------------------------------
__global__ void __launch_bounds__(128) k_y1() {
    int id = blockIdx.x;                 // 1024 blocks
    int m0 = (id >> 2) * 64;
    int n0 = (id & 3) * 64;
    mma_job(g_enc, Mn, 0, Mn, g_Udf, Mn / 8, g_y1, Mn, m0, n0);
}

// ---------------- per-batch attention + LSTM cell update ------------------
__global__ void __launch_bounds__(256) k_attn(
        const float* __restrict__ y_in, const float* __restrict__ v_d,
        const float* __restrict__ w_til, const float* __restrict__ b_wt,
        const float* __restrict__ W_ih, const float* __restrict__ b_Wd,
        int t_step) {
    int b = blockIdx.x, tid = threadIdx.x;
    int warp = tid >> 5, lane = tid & 31;
    __shared__ float sx[Mn], sv[Mn], sl[Tn], sred[8];
    __shared__ float s_ytil;

    {   // x1 = sum of NSX split-K partials + bias
        int o = b * Mn + tid;
        float v = b_Wd[tid];
#pragma unroll
        for (int s = 0; s < NSX; s++) v += g_x1p[s * (Bn * Mn) + o];
        sx[tid] = v;
    }
    sv[tid] = v_d[tid];
    __syncthreads();

    const float* y1b = g_y1 + (size_t)b * Tn * Mn;
#pragma unroll
    for (int i = 0; i < 8; i++) {
        int t = warp * 8 + i;
        const float* row = y1b + t * Mn;
        float acc = 0.f;
#pragma unroll
        for (int j = 0; j < 8; j++) {
            int m = lane + 32 * j;
            acc += tanh_mufu(sx[m] + row[m]) * sv[m];
        }
#pragma unroll
        for (int o = 16; o > 0; o >>= 1) acc += __shfl_xor_sync(0xffffffffu, acc, o);
        if (lane == 0) sl[t] = acc;
    }
    __syncthreads();

    if (warp == 0) {   // softmax over 64
        float v0 = sl[lane], v1 = sl[lane + 32];
        float mx = fmaxf(v0, v1);
#pragma unroll
        for (int o = 16; o > 0; o >>= 1) mx = fmaxf(mx, __shfl_xor_sync(0xffffffffu, mx, o));
        float e0 = __expf(v0 - mx), e1 = __expf(v1 - mx);
        float s = e0 + e1;
#pragma unroll
        for (int o = 16; o > 0; o >>= 1) s += __shfl_xor_sync(0xffffffffu, s, o);
        float inv = __fdividef(1.f, s);
        sl[lane] = e0 * inv; sl[lane + 32] = e1 * inv;
    }
    __syncthreads();

    const float* encb = g_enc + (size_t)b * Tn * Mn;
    float c = 0.f;
#pragma unroll 8
    for (int t = 0; t < Tn; t++) c += sl[t] * encb[t * Mn + tid];
    g_c[b * Mn + tid] = c;

    float part = c * w_til[tid];
#pragma unroll
    for (int o = 16; o > 0; o >>= 1) part += __shfl_xor_sync(0xffffffffu, part, o);
    if (lane == 0) sred[warp] = part;
    __syncthreads();
    if (tid == 0) {
        float s = 0.f;
#pragma unroll
        for (int w = 0; w < 8; w++) s += sred[w];
        s_ytil = s + w_til[Mn] * y_in[b * Tn + t_step] + b_wt[0];
    }
    __syncthreads();
    float yt = s_ytil;

    float gate[4];
#pragma unroll
    for (int q = 0; q < 4; q++) {
        int idx = q * Hn + tid;
        float v = g_gbias[idx] + yt * W_ih[idx];
#pragma unroll
        for (int s = 0; s < NSG; s++)
            v += g_G1p[s * (Bn * G4H) + b * G4H + idx];
        gate[q] = v;
    }
    float sp = g_S[b * K2H + Hn + tid];
    float spn = sigm(gate[1]) * sp + sigm(gate[0]) * tanh_acc(gate[2]);
    float dn  = sigm(gate[3]) * tanh_acc(spn);
    g_S[b * K2H + tid]      = dn;
    g_S[b * K2H + Hn + tid] = spn;
}

// ---------------- folded output: out[b] = [d|c] . wv + const --------------
__global__ void k_out(float* __restrict__ out) {
    int b = blockIdx.x, tid = threadIdx.x;
    int warp = tid >> 5, lane = tid & 31;
    __shared__ float sred[8];
    float p = g_S[b * K2H + tid] * g_wv[tid] + g_c[b * Mn + tid] * g_wv[Hn + tid];
#pragma unroll
    for (int o = 16; o > 0; o >>= 1) p += __shfl_xor_sync(0xffffffffu, p, o);
    if (lane == 0) sred[warp] = p;
    __syncthreads();
    if (tid == 0) {
        float s = 0.f;
#pragma unroll
        for (int w = 0; w < 8; w++) s += sred[w];
        out[b] = s + g_wv[512];
    }
}

extern "C" void kernel_launch(void* const* d_in, const int* in_sizes, int n_in,
                              void* d_out, int out_size) {
    const float* enc  = (const float*)d_in[0];
    const float* y    = (const float*)d_in[1];
    const float* W_d  = (const float*)d_in[2];
    const float* b_Wd = (const float*)d_in[3];
    const float* U_d  = (const float*)d_in[4];
    const float* v_d  = (const float*)d_in[5];
    const float* w_t  = (const float*)d_in[6];
    const float* b_wt = (const float*)d_in[7];
    const float* W_ih = (const float*)d_in[8];
    const float* W_hh = (const float*)d_in[9];
    const float* b_ih = (const float*)d_in[10];
    const float* b_hh = (const float*)d_in[11];
    const float* W_y  = (const float*)d_in[12];
    const float* b_Wy = (const float*)d_in[13];
    const float* v_y  = (const float*)d_in[14];
    const float* b_vy = (const float*)d_in[15];

    k_pre<<<2048, 256>>>(enc, b_ih, b_hh);
    k_wv<<<1, 512>>>(W_y, v_y, b_Wy, b_vy);
    k_mkfrag<<<((Mn / 8) * (K2H / 8) * 32) / 256, 256>>>(W_d, 0, Mn, K2H);
    k_mkfrag<<<((G4H / 8) * (Hn / 8) * 32) / 256, 256>>>(W_hh, 1, G4H, Hn);
    k_mkfrag<<<((Mn / 8) * (Mn / 8) * 32) / 256, 256>>>(U_d, 2, Mn, Mn);
    k_y1<<<1024, 128>>>();
    for (int t = 0; t < Tn; t++) {
        k_stepgemm<<<384, 128>>>();
        k_attn<<<256, 256>>>(y, v_d, w_t, b_wt, W_ih, b_Wd, t);
    }
    k_out<<<256, 256>>>((float*)d_out);
}

// round 10
// speedup vs baseline: 1.1653x; 1.0231x over previous
#include <cuda_runtime.h>
#include <cstdint>

namespace {
constexpr int Bn = 256, Tn = 64, Mn = 256, Hn = 256, K2H = 512, G4H = 1024;
constexpr int NSX = 8;   // split-K slices for x1 (K=512, slice 64)
constexpr int NSG = 4;   // split-K slices for G1 (K=256, slice 64)
constexpr int GRID_P = 384;
}

// ---------------- device scratch (no allocations allowed) ----------------
__device__ float g_enc[Bn * Tn * Mn];       // enc (b,t,m)
__device__ float g_y1 [Bn * Tn * Mn];       // enc @ U_d^T
__device__ float g_S  [Bn * K2H];           // [d | sp] per batch row
__device__ float g_x1p[NSX * Bn * Mn];      // x1 split-K partials
__device__ float g_G1p[NSG * Bn * G4H];     // G1 split-K partials
__device__ float g_gbias[G4H];              // b_ih + b_hh
__device__ float g_wv [513];                // folded W_y/v_y projection + const

// tf32 fragment-ordered weights (prepped once per launch)
__device__ float g_Wdf[(Mn / 8) * (K2H / 8) * 64];   // W_d   [256 x 512]
__device__ float g_Whf[(G4H / 8) * (Hn / 8) * 64];   // W_hh  [1024 x 256]
__device__ float g_Udf[(Mn / 8) * (Mn / 8) * 64];    // U_d   [256 x 256]

// dataflow counters (monotonic within one launch; reset by k_pre)
__device__ unsigned g_x1cnt[4];             // x1 jobs done per m-group (32/step)
__device__ unsigned g_g1cnt[4];             // G1 jobs done per m-group (64/step)
__device__ unsigned g_scnt [4];             // attn/LSTM done per batch-group (64/step)

__device__ __forceinline__ float tanh_mufu(float x) {      // attention only
    float y; asm("tanh.approx.f32 %0, %1;" : "=f"(y) : "f"(x)); return y;
}
__device__ __forceinline__ float tanh_acc(float x) {       // LSTM gates
    float e = __expf(2.f * x);
    return 1.f - __fdividef(2.f, e + 1.f);
}
__device__ __forceinline__ float sigm(float x) {
    return __fdividef(1.f, 1.f + __expf(-x));
}
__device__ __forceinline__ uint32_t to_tf32(float f) {
    uint32_t u; asm("cvt.rna.tf32.f32 %0, %1;" : "=r"(u) : "f"(f)); return u;
}
__device__ __forceinline__ void mma_tf32(float acc[4], uint4 a,
                                         uint32_t b0, uint32_t b1) {
    asm volatile(
        "mma.sync.aligned.m16n8k8.row.col.f32.tf32.tf32.f32 "
        "{%0,%1,%2,%3}, {%4,%5,%6,%7}, {%8,%9}, {%0,%1,%2,%3};"
        : "+f"(acc[0]), "+f"(acc[1]), "+f"(acc[2]), "+f"(acc[3])
        : "r"(a.x), "r"(a.y), "r"(a.z), "r"(a.w), "r"(b0), "r"(b1));
}
__device__ __forceinline__ void wait_ge(const unsigned* p, unsigned tgt) {
    while (*(volatile const unsigned*)p < tgt) __nanosleep(32);
}

// ---------------- prep: transpose enc, zero state/counters, fold bias ----
__global__ void k_pre(const float* __restrict__ enc_in,
                      const float* __restrict__ b_ih,
                      const float* __restrict__ b_hh) {
    int idx = blockIdx.x * blockDim.x + threadIdx.x;
    int stride = gridDim.x * blockDim.x;
    for (int i = idx; i < Bn * Tn * Mn; i += stride) {
        int m = i & (Mn - 1);
        int t = (i >> 8) & (Tn - 1);
        int b = i >> 14;
        g_enc[i] = enc_in[(size_t)t * Bn * Mn + (size_t)b * Mn + m];
    }
    for (int i = idx; i < Bn * K2H; i += stride) g_S[i] = 0.f;
    for (int i = idx; i < G4H; i += stride) g_gbias[i] = b_ih[i] + b_hh[i];
    if (idx < 4) { g_x1cnt[idx] = 0u; g_g1cnt[idx] = 0u; g_scnt[idx] = 0u; }
}

// ---------------- fold final projection ----------------------------------
__global__ void k_wv(const float* __restrict__ W_y, const float* __restrict__ v_y,
                     const float* __restrict__ b_Wy, const float* __restrict__ b_vy) {
    int k = threadIdx.x;  // 512 threads
    float s = 0.f;
    for (int j = 0; j < Hn; j++) s += v_y[j] * W_y[(size_t)j * K2H + k];
    g_wv[k] = s;
    if (k == 0) {
        float s0 = 0.f;
        for (int j = 0; j < Hn; j++) s0 += v_y[j] * b_Wy[j];
        g_wv[512] = s0 + b_vy[0];
    }
}

// ---------------- weight -> tf32 fragment order (dst resolved ON DEVICE) --
__global__ void k_mkfrag(const float* __restrict__ src, int which,
                         int N, int K) {
    float* dst = (which == 0) ? g_Wdf : (which == 1) ? g_Whf : g_Udf;
    int id = blockIdx.x * blockDim.x + threadIdx.x;
    int total = (N >> 3) * (K >> 3) * 32;
    if (id >= total) return;
    int lane = id & 31;
    int kk = (id >> 5) % (K >> 3);
    int j8 = (id >> 5) / (K >> 3);
    int n  = j8 * 8 + (lane >> 2);
    int k0 = kk * 8 + (lane & 3);
    dst[id * 2 + 0] = __uint_as_float(to_tf32(src[(size_t)n * K + k0]));
    dst[id * 2 + 1] = __uint_as_float(to_tf32(src[(size_t)n * K + k0 + 4]));
}

// ---------------- tf32 MMA building blocks --------------------------------
// Bf: contiguous coalesced copy of a 64n x 64k fragment slice (16KB).
__device__ __forceinline__ void load_Bf(float* __restrict__ Bf,
                                        const float* __restrict__ Wf, int Kfr,
                                        int n0, int kkb, int tid) {
#pragma unroll
    for (int it = 0; it < 8; it++) {
        int idx = tid + it * 128;              // float4 unit 0..1023
        int chunk = idx >> 4;                  // = j*8 + kkl
        int j = chunk >> 3, kkl = chunk & 7;
        const float* sp = Wf
            + ((size_t)((n0 >> 3) + j) * Kfr + kkb + kkl) * 64
            + (idx & 15) * 4;
        *(float4*)(Bf + (idx << 2)) = *(const float4*)sp;
    }
}

// Stage A rows [m0,m0+64) x k [kabs,kabs+64) into fragment-ordered Af.
__device__ __forceinline__ void stage_A(const float* __restrict__ A, int lda,
                                        int m0, int kabs,
                                        uint32_t* __restrict__ Af, int tid) {
    const int r = tid >> 1;
    const int khalf = (tid & 1) * 32;
    const int wv = r >> 4;
    const int lanebase = (r & 7) * 4;
    const int regbase0 = (r & 15) >> 3;
    const float* Ap = A + (size_t)(m0 + r) * lda + kabs + khalf;
    float4 av8[8];
#pragma unroll
    for (int i = 0; i < 8; i++) av8[i] = *(const float4*)(Ap + i * 4);
#pragma unroll
    for (int i = 0; i < 8; i++) {
        int kloc = khalf + i * 4;
        int kk = kloc >> 3;
        int reg = regbase0 + ((kloc & 7) >> 2) * 2;
        uint32_t* dp = Af + ((wv * 8 + kk) * 32 + lanebase) * 4 + reg;
        dp[0]  = to_tf32(av8[i].x);
        dp[4]  = to_tf32(av8[i].y);
        dp[8]  = to_tf32(av8[i].z);
        dp[12] = to_tf32(av8[i].w);
    }
}

__device__ __forceinline__ void mma_inner(const uint32_t* __restrict__ Af,
                                          const float* __restrict__ Bf,
                                          float acc[8][4], int w, int lane) {
#pragma unroll
    for (int kkl = 0; kkl < 8; kkl++) {
        uint4 av = *(const uint4*)(Af + ((w * 8 + kkl) * 32 + lane) * 4);
#pragma unroll
        for (int j = 0; j < 8; j++) {
            float2 b = *(const float2*)(Bf + (j * 8 + kkl) * 64 + lane * 2);
            mma_tf32(acc[j], av, __float_as_uint(b.x), __float_as_uint(b.y));
        }
    }
}

__device__ __forceinline__ void store_acc(float* __restrict__ C, int ldc,
                                          int m0, int n0, float acc[8][4],
                                          int w, int lane) {
    const int mrow = m0 + w * 16 + (lane >> 2);
    const int nc0  = n0 + (lane & 3) * 2;
#pragma unroll
    for (int j = 0; j < 8; j++) {
        float2 v0; v0.x = acc[j][0]; v0.y = acc[j][1];
        float2 v1; v1.x = acc[j][2]; v1.y = acc[j][3];
        *(float2*)(C + (size_t)mrow * ldc + nc0 + j * 8) = v0;
        *(float2*)(C + (size_t)(mrow + 8) * ldc + nc0 + j * 8) = v1;
    }
}

// ---------------- one-time y1 GEMM (tf32, K=256 = 4 chunks) ----------------
__global__ void __launch_bounds__(128) k_y1() {
    __shared__ __align__(16) uint32_t Af[4096];
    __shared__ __align__(16) float    Bf[4096];
    int id = blockIdx.x;                 // 1024 blocks
    int tid = threadIdx.x;
    int w = tid >> 5, lane = tid & 31;
    int m0 = (id >> 2) * 64, n0 = (id & 3) * 64;
    float acc[8][4];
#pragma unroll
    for (int j = 0; j < 8; j++)
#pragma unroll
        for (int q = 0; q < 4; q++) acc[j][q] = 0.f;
    for (int c = 0; c < 4; c++) {
        if (c) __syncthreads();
        load_Bf(Bf, g_Udf, Mn / 8, n0, c * 8, tid);
        stage_A(g_enc, Mn, m0, c * 64, Af, tid);
        __syncthreads();
        mma_inner(Af, Bf, acc, w, lane);
    }
    store_acc(g_y1, Mn, m0, n0, acc, w, lane);
}

// ---------------- attention + LSTM body (128 threads, one batch b) --------
__device__ __forceinline__ void attn_body(
        int b, int t_step,
        const float* __restrict__ y_in, const float* __restrict__ v_d,
        const float* __restrict__ w_til, const float* __restrict__ b_wt,
        const float* __restrict__ W_ih, const float* __restrict__ b_Wd,
        float* __restrict__ out) {
    const int tid = threadIdx.x;
    const int warp = tid >> 5, lane = tid & 31;
    __shared__ float sx[Mn], sv[Mn], sl[Tn], sred[4];
    __shared__ float s_ytil;

#pragma unroll
    for (int e = 0; e < 2; e++) {
        int m = tid + e * 128;
        int o = b * Mn + m;
        float v = b_Wd[m];
#pragma unroll
        for (int s = 0; s < NSX; s++) v += g_x1p[s * (Bn * Mn) + o];
        sx[m] = v;
        sv[m] = v_d[m];
    }
    __syncthreads();

    const float* y1b = g_y1 + (size_t)b * Tn * Mn;
#pragma unroll
    for (int i = 0; i < 16; i++) {
        int t = warp * 16 + i;
        const float* row = y1b + t * Mn;
        float acc = 0.f;
#pragma unroll
        for (int j = 0; j < 8; j++) {
            int m = lane + 32 * j;
            acc += tanh_mufu(sx[m] + row[m]) * sv[m];
        }
#pragma unroll
        for (int o = 16; o > 0; o >>= 1) acc += __shfl_xor_sync(0xffffffffu, acc, o);
        if (lane == 0) sl[t] = acc;
    }
    __syncthreads();

    if (warp == 0) {   // softmax over 64
        float v0 = sl[lane], v1 = sl[lane + 32];
        float mx = fmaxf(v0, v1);
#pragma unroll
        for (int o = 16; o > 0; o >>= 1) mx = fmaxf(mx, __shfl_xor_sync(0xffffffffu, mx, o));
        float e0 = __expf(v0 - mx), e1 = __expf(v1 - mx);
        float s = e0 + e1;
#pragma unroll
        for (int o = 16; o > 0; o >>= 1) s += __shfl_xor_sync(0xffffffffu, s, o);
        float inv = __fdividef(1.f, s);
        sl[lane] = e0 * inv; sl[lane + 32] = e1 * inv;
    }
    __syncthreads();

    const float* encb = g_enc + (size_t)b * Tn * Mn;
    float c0 = 0.f, c1 = 0.f;
#pragma unroll 8
    for (int t = 0; t < Tn; t++) {
        float bta = sl[t];
        c0 += bta * encb[t * Mn + tid];
        c1 += bta * encb[t * Mn + tid + 128];
    }

    float part = c0 * w_til[tid] + c1 * w_til[tid + 128];
#pragma unroll
    for (int o = 16; o > 0; o >>= 1) part += __shfl_xor_sync(0xffffffffu, part, o);
    if (lane == 0) sred[warp] = part;
    __syncthreads();
    if (tid == 0)
        s_ytil = sred[0] + sred[1] + sred[2] + sred[3]
               + w_til[Mn] * y_in[b * Tn + t_step] + b_wt[0];
    __syncthreads();
    float yt = s_ytil;

    float dnv[2];
#pragma unroll
    for (int e = 0; e < 2; e++) {
        int h = tid + e * 128;
        float gate[4];
#pragma unroll
        for (int q = 0; q < 4; q++) {
            int idx = q * Hn + h;
            float v = g_gbias[idx] + yt * W_ih[idx];
#pragma unroll
            for (int s = 0; s < NSG; s++)
                v += g_G1p[s * (Bn * G4H) + b * G4H + idx];
            gate[q] = v;
        }
        float sp = g_S[b * K2H + Hn + h];
        float spn = sigm(gate[1]) * sp + sigm(gate[0]) * tanh_acc(gate[2]);
        float dn  = sigm(gate[3]) * tanh_acc(spn);
        g_S[b * K2H + h]      = dn;
        g_S[b * K2H + Hn + h] = spn;
        dnv[e] = dn;
    }

    if (t_step == Tn - 1) {   // folded output
        float p = dnv[0] * g_wv[tid] + dnv[1] * g_wv[tid + 128]
                + c0 * g_wv[Hn + tid] + c1 * g_wv[Hn + tid + 128];
#pragma unroll
        for (int o = 16; o > 0; o >>= 1) p += __shfl_xor_sync(0xffffffffu, p, o);
        __syncthreads();
        if (lane == 0) sred[warp] = p;
        __syncthreads();
        if (tid == 0) out[b] = sred[0] + sred[1] + sred[2] + sred[3] + g_wv[512];
    }
}

// ---------------- persistent recurrence kernel ----------------------------
// 384 blocks x 128 threads, all co-resident (3/SM via launch_bounds).
// Per step: one tf32 64x64x64 GEMM job per block (weights SMEM-resident for
// the whole kernel); blocks 0..255 then run attn+LSTM for batch b=bid.
// Dependencies via monotonic per-group counters.
__global__ void __launch_bounds__(128, 3) k_persist(
        const float* __restrict__ y_in,  const float* __restrict__ v_d,
        const float* __restrict__ w_til, const float* __restrict__ b_wt,
        const float* __restrict__ W_ih,  const float* __restrict__ b_Wd,
        float* __restrict__ out) {
    __shared__ __align__(16) uint32_t Af[4096];
    __shared__ __align__(16) float    Bf[4096];

    const int bid = blockIdx.x;
    const int tid = threadIdx.x;
    const int w = tid >> 5, lane = tid & 31;

    // decode this block's fixed GEMM job
    const float* jWf; float* jC;
    int jKfr, jldc, jm0, jn0, jkb, jgrp;
    unsigned* jcnt;
    if (bid < 128) {                      // x1: S @ W_d^T, 4m x 4n x 8 slices
        int s = bid & 7;
        jn0 = ((bid >> 3) & 3) * 64; jm0 = (bid >> 5) * 64;
        jkb = s * 64; jWf = g_Wdf; jKfr = K2H / 8;
        jC = g_x1p + s * (Bn * Mn); jldc = Mn;
        jgrp = bid >> 5; jcnt = &g_x1cnt[jgrp];
    } else {                              // G1: d @ W_hh^T, 4m x 16n x 4 slices
        int j = bid - 128;
        int s = j & 3;
        jn0 = ((j >> 2) & 15) * 64; jm0 = (j >> 6) * 64;
        jkb = s * 64; jWf = g_Whf; jKfr = Hn / 8;
        jC = g_G1p + s * (Bn * G4H); jldc = G4H;
        jgrp = j >> 6; jcnt = &g_g1cnt[jgrp];
    }
    const int agrp = bid >> 6;            // attn batch-group (bid < 256)

    // weights never change: stage B fragments once for the whole kernel
    load_Bf(Bf, jWf, jKfr, jn0, jkb >> 3, tid);

    for (int t = 0; t < Tn; t++) {
        // ---- GEMM: needs S rows of group jgrp updated through step t-1
        if (t > 0) {
            if (tid == 0) { wait_ge(&g_scnt[jgrp], 64u * (unsigned)t); __threadfence(); }
            __syncthreads();
        }
        float acc[8][4];
#pragma unroll
        for (int j = 0; j < 8; j++)
#pragma unroll
            for (int q = 0; q < 4; q++) acc[j][q] = 0.f;
        stage_A(g_S, K2H, jm0, jkb, Af, tid);
        __syncthreads();                  // Af ready (also covers Bf at t=0)
        mma_inner(Af, Bf, acc, w, lane);
        store_acc(jC, jldc, jm0, jn0, acc, w, lane);
        __syncthreads();
        if (tid == 0) { __threadfence(); atomicAdd(jcnt, 1u); }

        // ---- attention + LSTM for batch bid (blocks 0..255)
        if (bid < 256) {
            if (tid == 0) {
                wait_ge(&g_x1cnt[agrp], 32u * (unsigned)(t + 1));
                wait_ge(&g_g1cnt[agrp], 64u * (unsigned)(t + 1));
                __threadfence();
            }
            __syncthreads();
            attn_body(bid, t, y_in, v_d, w_til, b_wt, W_ih, b_Wd, out);
            __syncthreads();
            if (tid == 0) { __threadfence(); atomicAdd(&g_scnt[agrp], 1u); }
        }
    }
}

extern "C" void kernel_launch(void* const* d_in, const int* in_sizes, int n_in,
                              void* d_out, int out_size) {
    const float* enc  = (const float*)d_in[0];
    const float* y    = (const float*)d_in[1];
    const float* W_d  = (const float*)d_in[2];
    const float* b_Wd = (const float*)d_in[3];
    const float* U_d  = (const float*)d_in[4];
    const float* v_d  = (const float*)d_in[5];
    const float* w_t  = (const float*)d_in[6];
    const float* b_wt = (const float*)d_in[7];
    const float* W_ih = (const float*)d_in[8];
    const float* W_hh = (const float*)d_in[9];
    const float* b_ih = (const float*)d_in[10];
    const float* b_hh = (const float*)d_in[11];
    const float* W_y  = (const float*)d_in[12];
    const float* b_Wy = (const float*)d_in[13];
    const float* v_y  = (const float*)d_in[14];
    const float* b_vy = (const float*)d_in[15];

    k_pre<<<2048, 256>>>(enc, b_ih, b_hh);
    k_wv<<<1, 512>>>(W_y, v_y, b_Wy, b_vy);
    k_mkfrag<<<((Mn / 8) * (K2H / 8) * 32) / 256, 256>>>(W_d, 0, Mn, K2H);
    k_mkfrag<<<((G4H / 8) * (Hn / 8) * 32) / 256, 256>>>(W_hh, 1, G4H, Hn);
    k_mkfrag<<<((Mn / 8) * (Mn / 8) * 32) / 256, 256>>>(U_d, 2, Mn, Mn);
    k_y1<<<1024, 128>>>();
    k_persist<<<GRID_P, 128>>>(y, v_d, w_t, b_wt, W_ih, b_Wd, (float*)d_out);
}